// round 15
// baseline (speedup 1.0000x reference)
#include <cuda_runtime.h>

// GaussianHistogram: hist[b,i,j] = sum_n exp(-pi*(f1-i)^2) * exp(-pi*(f2-j)^2) * mask
// (SIGMA = DELTA/sqrt(2pi) makes the exponent exactly -pi*d^2 and COEF == 1.0.)
//
// Fused single-kernel, skew-free version of R13:
//   phase 1 (scatter): 3 16B-aligned v4 REDs per sample (L1tex-wavefront
//     floor; ~2.26 cyc per divergent RED-lane/SM, fit over R3-R8). Alignment
//     guaranteed by splitting samples between out (r=0) and a column-shifted
//     scratch S2 (r=2), r = (i2-1)&2. Work is pulled DYNAMICALLY in 128-sample
//     chunks via an atomic counter -> near-zero finish-time skew at the grid
//     barrier (the R14 regression was static-partition imbalance, 512 blocks
//     over ~3.46 slots/SM, amplified by the barrier).
//   grid barrier: arrive+spin; 592 blocks with __launch_bounds__(128,8)
//     -> capacity 1184 co-resident, 2x slack, no deadlock.
//   phase 2 (fold): THREAD-LOCAL (R13, race-free): each thread reads only its
//     OWN S2 float4 slots, REDs them +2 columns into out with two coalesced
//     8B v2 REDs, zero-stores only its own slots. S2 cols 252..255 are never
//     written (scatter windows end <= 251) -> boundary slots permanently zero,
//     skipped deterministically.
//   counters self-reset via a done-counter so every graph replay is identical.

#define GH_BINS    256
#define GH_LOGN    15                  // N = 32768 per batch
#define GH_TOTALH  (8 * 65536)         // B * BINS * BINS = 524288
#define GH_SLOTS   (GH_TOTALH / 4)     // 131072 float4 fold slots
#define GH_GRID    592                 // 4 * 148; <= half of guaranteed residency
#define GH_THREADS 128
#define GH_CHUNK   128                 // samples per work item (== blockDim)

__device__ float gh_s2[GH_TOTALH];     // 2 MB, zero-invariant
__device__ unsigned int gh_work = 0;
__device__ unsigned int gh_bar  = 0;
__device__ unsigned int gh_done = 0;

__device__ __forceinline__ void gh_scatter_one(int idx,
                                               const float* __restrict__ x1,
                                               const float* __restrict__ x2,
                                               const float* __restrict__ mask,
                                               float* __restrict__ out)
{
    int b = idx >> GH_LOGN;            // batch index (N = 32768)

    float a1 = x1[idx];
    float a2 = x2[idx];
    float m  = mask[idx];

    // continuous bin coordinate: f = (x - MIN_V)/DELTA - 0.5 ; center c_i at f == i
    const float INV_DELTA = 256.0f / 1.5f;
    float f1 = (a1 + 0.25f) * INV_DELTA - 0.5f;
    float f2 = (a2 + 0.25f) * INV_DELTA - 0.5f;

    int i1 = (int)floorf(f1 + 0.5f);
    int i2 = (int)floorf(f2 + 0.5f);
    i1 = min(max(i1, 1), GH_BINS - 2);      // OOB insurance (x in [0,1))
    i2 = min(max(i2, 1), GH_BINS - 2);

    float u1 = f1 - (float)i1;
    float u2 = f2 - (float)i2;

    const float NPI_L2E = -4.53236014182719f;   // -pi * log2(e)

    float dm = u1 + 1.0f, dp = u1 - 1.0f;
    float w0 = exp2f(NPI_L2E * dm * dm);
    float w1 = exp2f(NPI_L2E * u1 * u1);
    float w2 = exp2f(NPI_L2E * dp * dp);

    float em = u2 + 1.0f, ep = u2 - 1.0f;
    float t0 = exp2f(NPI_L2E * em * em) * m;
    float t1 = exp2f(NPI_L2E * u2 * u2) * m;
    float t2 = exp2f(NPI_L2E * ep * ep) * m;

    // taps at cols a..a+2, a = i2-1 in [0,253].
    // r = a&2: with am = a-r, am&3 in {0,1} -> taps fit one aligned v4 window.
    int a   = i2 - 1;
    int r   = a & 2;                   // 0 -> out, 2 -> S2 replica (shifted -2)
    int am  = a - r;
    int w   = am & ~3;                 // window start, [0,248]
    bool od = (am & 1) != 0;

    float g0 = od ? 0.0f : t0;
    float g1 = od ? t0   : t1;
    float g2 = od ? t1   : t2;
    float g3 = od ? t2   : 0.0f;

    size_t off = ((size_t)b << 16) + (size_t)(i1 - 1) * GH_BINS + w;
    float* base = (r == 0) ? (out + off) : (gh_s2 + off);

    float p0 = w0*g0, p1 = w0*g1, p2 = w0*g2, p3 = w0*g3;
    asm volatile("red.global.add.v4.f32 [%0], {%1,%2,%3,%4};"
                 :: "l"(base), "f"(p0), "f"(p1), "f"(p2), "f"(p3) : "memory");
    p0 = w1*g0; p1 = w1*g1; p2 = w1*g2; p3 = w1*g3;
    asm volatile("red.global.add.v4.f32 [%0], {%1,%2,%3,%4};"
                 :: "l"(base + GH_BINS), "f"(p0), "f"(p1), "f"(p2), "f"(p3) : "memory");
    p0 = w2*g0; p1 = w2*g1; p2 = w2*g2; p3 = w2*g3;
    asm volatile("red.global.add.v4.f32 [%0], {%1,%2,%3,%4};"
                 :: "l"(base + 2*GH_BINS), "f"(p0), "f"(p1), "f"(p2), "f"(p3) : "memory");
}

__global__ void __launch_bounds__(GH_THREADS, 8)
gh_fused_kernel(const float* __restrict__ x1,
                const float* __restrict__ x2,
                const float* __restrict__ mask,
                float* __restrict__ out,
                int total)
{
    __shared__ int sh_chunk;
    int nchunks = (total + GH_CHUNK - 1) / GH_CHUNK;   // 2048

    // ---- phase 1: dynamically scheduled scatter ----
    for (;;) {
        if (threadIdx.x == 0)
            sh_chunk = (int)atomicAdd(&gh_work, 1u);
        __syncthreads();
        int c = sh_chunk;
        __syncthreads();                // sh_chunk reusable next iteration
        if (c >= nchunks) break;
        int idx = c * GH_CHUNK + threadIdx.x;
        if (idx < total)
            gh_scatter_one(idx, x1, x2, mask, out);
    }

    // ---- grid barrier (all 592 blocks co-resident: capacity is 8/SM) ----
    if (threadIdx.x == 0) {
        __threadfence();                       // order REDs before arrive
        atomicAdd(&gh_bar, 1u);
        while (*(volatile unsigned int*)&gh_bar < GH_GRID)
            __nanosleep(32);
    }
    __syncthreads();
    __threadfence();                           // acquire side

    // ---- phase 2: thread-local fold (grid-stride over float4 slots) ----
    // S2[b,i,jj] contributes to out[b,i,jj+2]: push own cols j..j+3 into out
    // cols j+2..j+5 with two coalesced v2 REDs, zero own slot. Slots with any
    // mass have col <= 251, so +5 stays within the row.
    {
        int nthreads = GH_GRID * GH_THREADS;   // 75776
        int t = blockIdx.x * GH_THREADS + threadIdx.x;
        for (int s = t; s < GH_SLOTS; s += nthreads) {
            int base = s * 4;
            float4 v = *reinterpret_cast<const float4*>(gh_s2 + base);
            float sum = fabsf(v.x) + fabsf(v.y) + fabsf(v.z) + fabsf(v.w);
            if (sum != 0.0f) {
                asm volatile("red.global.add.v2.f32 [%0], {%1,%2};"
                             :: "l"(out + base + 2), "f"(v.x), "f"(v.y) : "memory");
                asm volatile("red.global.add.v2.f32 [%0], {%1,%2};"
                             :: "l"(out + base + 4), "f"(v.z), "f"(v.w) : "memory");
                *reinterpret_cast<float4*>(gh_s2 + base) =
                    make_float4(0.f, 0.f, 0.f, 0.f);
            }
        }
    }

    // ---- counter self-reset for the next graph replay ----
    __syncthreads();
    if (threadIdx.x == 0) {
        __threadfence();
        unsigned int vdone = atomicAdd(&gh_done, 1u);
        if (vdone == GH_GRID - 1) {            // last block: all past gh_bar
            gh_work = 0;
            gh_bar  = 0;
            gh_done = 0;
            __threadfence();
        }
    }
}

extern "C" void kernel_launch(void* const* d_in, const int* in_sizes, int n_in,
                              void* d_out, int out_size)
{
    const float* x1   = (const float*)d_in[0];
    const float* x2   = (const float*)d_in[1];
    const float* mask = (const float*)d_in[2];
    float* out = (float*)d_out;

    // out accumulates REDs directly -> zero it (memset node; graph-capturable)
    cudaMemsetAsync(d_out, 0, (size_t)out_size * sizeof(float));

    int total = in_sizes[0];               // B*N = 262144
    gh_fused_kernel<<<GH_GRID, GH_THREADS>>>(x1, x2, mask, out, total);
}

// round 16
// speedup vs baseline: 1.5013x; 1.5013x over previous
#include <cuda_runtime.h>

// GaussianHistogram: hist[b,i,j] = sum_n exp(-pi*(f1-i)^2) * exp(-pi*(f2-j)^2) * mask
// (SIGMA = DELTA/sqrt(2pi) makes the exponent exactly -pi*d^2 and COEF == 1.0.)
//
// Two-kernel structure (fusion falsified in R12-R14: grid-barrier + occupancy
// tax exceeds one launch):
//   scatter: 3 16B-aligned v4 REDs per sample — the L1tex-wavefront floor
//     (~2.26 cyc per divergent RED-lane/SM, fit over R3-R8). Alignment
//     guaranteed by splitting samples between out (r=0) and a column-shifted
//     scratch S2 (r=2), r = (i2-1)&2. 1024x256 grid (57% occ, proven in R6).
//   fold: out[b,i,jj+2] += S2[b,i,jj], race-free forward push. R8's fold was
//     MLP-starved (1 load/thread -> ~1.6TB/s -> 5.2us); here 32768 threads
//     each FRONT-BATCH 4 float4 loads (MLP=4) -> ~4x effective bandwidth.
//     Each thread touches only its OWN slots (reads, REDs, zero-stores), so
//     no cross-thread hazard. Contributions are all >= 0, so the zero-skip
//     guard is value-deterministic. Nonzero S2 slots end at col <= 251 ->
//     the +2 push never crosses a row boundary.

#define GH_BINS    256
#define GH_LOGN    15                  // N = 32768 per batch
#define GH_TOTALH  (8 * 65536)         // B * BINS * BINS = 524288
#define GH_SLOTS   (GH_TOTALH / 4)     // 131072 float4 slots
#define GH_FBLOCKS 128
#define GH_FTHREADS 256
#define GH_FN      (GH_FBLOCKS * GH_FTHREADS)   // 32768 fold threads, 4 slots each

__device__ float gh_s2[GH_TOTALH];     // 2 MB, zero-invariant (BSS-zero at load)

__global__ void __launch_bounds__(256)
gh_scatter_kernel(const float* __restrict__ x1,
                  const float* __restrict__ x2,
                  const float* __restrict__ mask,
                  float* __restrict__ out,
                  int total)
{
    int idx = blockIdx.x * blockDim.x + threadIdx.x;
    if (idx >= total) return;

    int b = idx >> GH_LOGN;            // batch index (N = 32768)

    float a1 = x1[idx];
    float a2 = x2[idx];
    float m  = mask[idx];

    // continuous bin coordinate: f = (x - MIN_V)/DELTA - 0.5 ; center c_i at f == i
    const float INV_DELTA = 256.0f / 1.5f;
    float f1 = (a1 + 0.25f) * INV_DELTA - 0.5f;
    float f2 = (a2 + 0.25f) * INV_DELTA - 0.5f;

    int i1 = (int)floorf(f1 + 0.5f);
    int i2 = (int)floorf(f2 + 0.5f);
    i1 = min(max(i1, 1), GH_BINS - 2);      // OOB insurance (x in [0,1))
    i2 = min(max(i2, 1), GH_BINS - 2);

    float u1 = f1 - (float)i1;
    float u2 = f2 - (float)i2;

    const float NPI_L2E = -4.53236014182719f;   // -pi * log2(e)

    float dm = u1 + 1.0f, dp = u1 - 1.0f;
    float w0 = exp2f(NPI_L2E * dm * dm);
    float w1 = exp2f(NPI_L2E * u1 * u1);
    float w2 = exp2f(NPI_L2E * dp * dp);

    float em = u2 + 1.0f, ep = u2 - 1.0f;
    float t0 = exp2f(NPI_L2E * em * em) * m;
    float t1 = exp2f(NPI_L2E * u2 * u2) * m;
    float t2 = exp2f(NPI_L2E * ep * ep) * m;

    // taps at cols a..a+2, a = i2-1 in [0,253].
    // r = a&2: with am = a-r, am&3 in {0,1} -> taps fit one aligned v4 window.
    int a   = i2 - 1;
    int r   = a & 2;                   // 0 -> out, 2 -> S2 replica (shifted -2)
    int am  = a - r;
    int w   = am & ~3;                 // aligned window start
    bool od = (am & 1) != 0;

    float g0 = od ? 0.0f : t0;
    float g1 = od ? t0   : t1;
    float g2 = od ? t1   : t2;
    float g3 = od ? t2   : 0.0f;

    size_t off = ((size_t)b << 16) + (size_t)(i1 - 1) * GH_BINS + w;
    float* base = (r == 0) ? (out + off) : (gh_s2 + off);

    float p0 = w0*g0, p1 = w0*g1, p2 = w0*g2, p3 = w0*g3;
    asm volatile("red.global.add.v4.f32 [%0], {%1,%2,%3,%4};"
                 :: "l"(base), "f"(p0), "f"(p1), "f"(p2), "f"(p3) : "memory");
    p0 = w1*g0; p1 = w1*g1; p2 = w1*g2; p3 = w1*g3;
    asm volatile("red.global.add.v4.f32 [%0], {%1,%2,%3,%4};"
                 :: "l"(base + GH_BINS), "f"(p0), "f"(p1), "f"(p2), "f"(p3) : "memory");
    p0 = w2*g0; p1 = w2*g1; p2 = w2*g2; p3 = w2*g3;
    asm volatile("red.global.add.v4.f32 [%0], {%1,%2,%3,%4};"
                 :: "l"(base + 2*GH_BINS), "f"(p0), "f"(p1), "f"(p2), "f"(p3) : "memory");
}

// Fold: for each owned S2 float4 slot (cols j..j+3): out[cols j+2..j+5] += it,
// then zero the slot. 4 slots per thread, loads FRONT-BATCHED for MLP=4.
__global__ void __launch_bounds__(GH_FTHREADS)
gh_fold_kernel(float* __restrict__ out)
{
    int t = blockIdx.x * GH_FTHREADS + threadIdx.x;

    // coalesced: consecutive threads -> consecutive slots within each batch
    int s0 = t;
    int s1 = t + GH_FN;
    int s2_ = t + 2 * GH_FN;
    int s3 = t + 3 * GH_FN;

    float4 v0 = *reinterpret_cast<const float4*>(gh_s2 + 4 * s0);
    float4 v1 = *reinterpret_cast<const float4*>(gh_s2 + 4 * s1);
    float4 v2 = *reinterpret_cast<const float4*>(gh_s2 + 4 * s2_);
    float4 v3 = *reinterpret_cast<const float4*>(gh_s2 + 4 * s3);

    const float4 z = make_float4(0.f, 0.f, 0.f, 0.f);

#define GH_FOLD_ONE(S, V)                                                     \
    {                                                                          \
        float _m = fabsf(V.x) + fabsf(V.y) + fabsf(V.z) + fabsf(V.w);          \
        if (_m != 0.0f) {                                                      \
            int _base = 4 * (S);                                               \
            asm volatile("red.global.add.v2.f32 [%0], {%1,%2};"                \
                         :: "l"(out + _base + 2), "f"(V.x), "f"(V.y)           \
                         : "memory");                                          \
            asm volatile("red.global.add.v2.f32 [%0], {%1,%2};"                \
                         :: "l"(out + _base + 4), "f"(V.z), "f"(V.w)           \
                         : "memory");                                          \
            *reinterpret_cast<float4*>(gh_s2 + _base) = z;                     \
        }                                                                      \
    }

    GH_FOLD_ONE(s0, v0)
    GH_FOLD_ONE(s1, v1)
    GH_FOLD_ONE(s2_, v2)
    GH_FOLD_ONE(s3, v3)
#undef GH_FOLD_ONE
}

extern "C" void kernel_launch(void* const* d_in, const int* in_sizes, int n_in,
                              void* d_out, int out_size)
{
    const float* x1   = (const float*)d_in[0];
    const float* x2   = (const float*)d_in[1];
    const float* mask = (const float*)d_in[2];
    float* out = (float*)d_out;

    // out accumulates REDs directly -> zero it (memset node; graph-capturable)
    cudaMemsetAsync(d_out, 0, (size_t)out_size * sizeof(float));

    int total = in_sizes[0];               // B*N = 262144
    int threads = 256;
    int blocks = (total + threads - 1) / threads;   // 1024
    gh_scatter_kernel<<<blocks, threads>>>(x1, x2, mask, out, total);

    gh_fold_kernel<<<GH_FBLOCKS, GH_FTHREADS>>>(out);
}